// round 14
// baseline (speedup 1.0000x reference)
#include <cuda_runtime.h>
#include <cuda_bf16.h>
#include <math.h>

// Problem constants
#define B    256
#define T    2048
#define D    64
#define N    128
#define LEAK 0.5f

// ---------------------------------------------------------------------------
// XLA ElementalIrEmitter::EmitTanh replica — VERIFIED BITWISE vs reference.
// ---------------------------------------------------------------------------
__device__ __forceinline__ float tanh_xla(float x) {
    const float kClamp = 7.99881172180175781f;
    const float kTiny  = 0.0004f;
    float cx = fminf(fmaxf(x, -kClamp), kClamp);
    float x2 = __fmul_rn(cx, cx);
    float p = -2.76076847742355e-16f;
    p = __fmaf_rn(x2, p, 2.00018790482477e-13f);
    p = __fmaf_rn(x2, p, -8.60467152213735e-11f);
    p = __fmaf_rn(x2, p, 5.12229709037114e-08f);
    p = __fmaf_rn(x2, p, 1.48572235717979e-05f);
    p = __fmaf_rn(x2, p, 6.37261928875436e-04f);
    p = __fmaf_rn(x2, p, 4.89352455891786e-03f);
    p = __fmul_rn(cx, p);
    float q = 1.19825839466702e-06f;
    q = __fmaf_rn(x2, q, 1.18534705686654e-04f);
    q = __fmaf_rn(x2, q, 2.26843463243900e-03f);
    q = __fmaf_rn(x2, q, 4.89352518554385e-03f);
    float r = __fdiv_rn(p, q);
    return (fabsf(x) < kTiny) ? x : r;
}

#define HBAR() asm volatile("bar.sync 3, 64;" ::: "memory")

// ---------------------------------------------------------------------------
// Warp-specialized fused ESN kernel. One batch per CTA, 192 threads.
//   tid   0..63  : HELPER warps (wid 0,1) — x staging, u-chains (2 cols each,
//                  W_in in regs, verified ascending-d chain), output STG.
//   tid  64..191 : COMPUTE warps (wid 2..5, higher wid -> arbiter priority) —
//                  pure serial loop: LDS u, 128-FMA state chain, tanh, STS.
// u ring depth 4 (helpers produce u[t+2] during step t; consumed at step t).
// One __syncthreads per step; helpers sync among themselves with bar 3.
// ---------------------------------------------------------------------------
__global__ __launch_bounds__(192, 1) void esn_fused_kernel(
    const float* __restrict__ x,
    const float* __restrict__ W_in,
    const float* __restrict__ b_in,
    const float* __restrict__ W_res,
    const float* __restrict__ b_res,
    float* __restrict__ X)
{
    __shared__ __align__(16) float st[2][N];      // state double buffer
    __shared__ __align__(16) float uring[4][N];   // u values, 2-step lookahead
    __shared__ __align__(16) float xb[2][D];      // x rows (helpers only)

    const int tid = threadIdx.x;
    const int b   = blockIdx.x;
    const float* xrow = x + (size_t)b * T * D;
    float* Xb = X + (size_t)b * T * N;

    if (tid < 64) {
        // ================= HELPER PATH =================
        const int lane = tid;
        const int c0 = lane, c1 = lane + 64;

        float win0[D], win1[D];
#pragma unroll
        for (int d = 0; d < D; d++) {
            win0[d] = W_in[d * N + c0];
            win1[d] = W_in[d * N + c1];
        }
        const float bi0 = b_in[c0], bi1 = b_in[c1];

        // ---- prologue: fill uring[0..2] = u[0..2] ----
#pragma unroll
        for (int s = 0; s < 3; s++) {
            if (s == 2) HBAR();                       // xb[0] reads (s=0) done
            xb[s & 1][lane] = xrow[(size_t)s * D + lane];
            HBAR();
            const float4* xq = reinterpret_cast<const float4*>(xb[s & 1]);
            float a0 = 0.f, a1 = 0.f;
#pragma unroll
            for (int j = 0; j < D / 4; j++) {
                float4 c = xq[j];
                a0 = __fmaf_rn(c.x, win0[4 * j],     a0);
                a0 = __fmaf_rn(c.y, win0[4 * j + 1], a0);
                a0 = __fmaf_rn(c.z, win0[4 * j + 2], a0);
                a0 = __fmaf_rn(c.w, win0[4 * j + 3], a0);
                a1 = __fmaf_rn(c.x, win1[4 * j],     a1);
                a1 = __fmaf_rn(c.y, win1[4 * j + 1], a1);
                a1 = __fmaf_rn(c.z, win1[4 * j + 2], a1);
                a1 = __fmaf_rn(c.w, win1[4 * j + 3], a1);
            }
            uring[s][c0] = __fadd_rn(a0, bi0);
            uring[s][c1] = __fadd_rn(a1, bi1);
        }
        float xreg = xrow[(size_t)3 * D + lane];      // x[3] for step t=1
        __syncthreads();                              // bar A: uring ready
        // compute does t=0 epilogue here
        __syncthreads();                              // bar B

        for (int t = 1; t < T; t++) {
            if (t <= T - 3) {
                xb[t & 1][lane] = xreg;               // stage x[t+2]
            }
            HBAR();
            if (t <= T - 3) {
                const float4* xq =
                    reinterpret_cast<const float4*>(xb[t & 1]);
                float a0 = 0.f, a1 = 0.f;
#pragma unroll
                for (int j = 0; j < D / 4; j++) {
                    float4 c = xq[j];
                    a0 = __fmaf_rn(c.x, win0[4 * j],     a0);
                    a0 = __fmaf_rn(c.y, win0[4 * j + 1], a0);
                    a0 = __fmaf_rn(c.z, win0[4 * j + 2], a0);
                    a0 = __fmaf_rn(c.w, win0[4 * j + 3], a0);
                    a1 = __fmaf_rn(c.x, win1[4 * j],     a1);
                    a1 = __fmaf_rn(c.y, win1[4 * j + 1], a1);
                    a1 = __fmaf_rn(c.z, win1[4 * j + 2], a1);
                    a1 = __fmaf_rn(c.w, win1[4 * j + 3], a1);
                }
                uring[(t + 2) & 3][c0] = __fadd_rn(a0, bi0);
                uring[(t + 2) & 3][c1] = __fadd_rn(a1, bi1);
            }
            if (t <= T - 4) xreg = xrow[(size_t)(t + 3) * D + lane];
            if (t >= 2) {
                // store X[t-1] (st[(t-1)&1] stable until after this barrier)
                float v0 = st[(t - 1) & 1][c0];
                float v1 = st[(t - 1) & 1][c1];
                Xb[(size_t)(t - 1) * N + c0] = v0;
                Xb[(size_t)(t - 1) * N + c1] = v1;
            }
            __syncthreads();
        }
    } else {
        // ================= COMPUTE PATH =================
        const int n = tid - 64;

        float w[N];
#pragma unroll
        for (int k = 0; k < N; k++) w[k] = W_res[k * N + n];
        const float brv = b_res[n];

        __syncthreads();                              // bar A: uring ready

        // t = 0 epilogue
        float xv = __fmul_rn(LEAK, tanh_xla(uring[0][n]));
        st[0][n] = xv;
        Xb[n] = xv;                                   // X[0]
        __syncthreads();                              // bar B

        for (int t = 1; t < T; t++) {
            const float uthis = uring[t & 3][n];      // LDS early

            const float4* xp4 =
                reinterpret_cast<const float4*>(st[(t - 1) & 1]);
            float4 f0 = xp4[0];
            float4 f1 = xp4[1];
            float4 f2 = xp4[2];
            float4 f3 = xp4[3];
            float acc = 0.f;
#pragma unroll
            for (int j = 0; j < 32; j++) {
                float4 c = f0;
                f0 = f1; f1 = f2; f2 = f3;
                if (j < 28) f3 = xp4[j + 4];
                acc = __fmaf_rn(c.x, w[4 * j],     acc);
                acc = __fmaf_rn(c.y, w[4 * j + 1], acc);
                acc = __fmaf_rn(c.z, w[4 * j + 2], acc);
                acc = __fmaf_rn(c.w, w[4 * j + 3], acc);
            }

            float arg = __fadd_rn(__fadd_rn(uthis, acc), brv);
            float th  = tanh_xla(arg);
            xv = __fadd_rn(__fmul_rn(1.0f - LEAK, xv), __fmul_rn(LEAK, th));

            st[t & 1][n] = xv;
            __syncthreads();
        }
        Xb[(size_t)(T - 1) * N + n] = xv;             // X[T-1]
    }
}

// ---------------------------------------------------------------------------
extern "C" void kernel_launch(void* const* d_in, const int* in_sizes, int n_in,
                              void* d_out, int out_size)
{
    const float* x     = (const float*)d_in[0];
    const float* W_in  = (const float*)d_in[1];
    const float* b_in  = (const float*)d_in[2];
    const float* W_res = (const float*)d_in[3];
    const float* b_res = (const float*)d_in[4];
    float* X = (float*)d_out;

    esn_fused_kernel<<<B, 192>>>(x, W_in, b_in, W_res, b_res, X);
}

// round 15
// speedup vs baseline: 1.0168x; 1.0168x over previous
#include <cuda_runtime.h>
#include <cuda_bf16.h>
#include <math.h>

// Problem constants
#define B    256
#define T    2048
#define D    64
#define N    128
#define LEAK 0.5f

// ---------------------------------------------------------------------------
// XLA ElementalIrEmitter::EmitTanh replica — VERIFIED BITWISE vs reference.
// q-polynomial first so ptxas can launch the divide's RCP during the p-chain.
// ---------------------------------------------------------------------------
__device__ __forceinline__ float tanh_xla(float x) {
    const float kClamp = 7.99881172180175781f;
    const float kTiny  = 0.0004f;
    float cx = fminf(fmaxf(x, -kClamp), kClamp);
    float x2 = __fmul_rn(cx, cx);
    float q = 1.19825839466702e-06f;
    q = __fmaf_rn(x2, q, 1.18534705686654e-04f);
    q = __fmaf_rn(x2, q, 2.26843463243900e-03f);
    q = __fmaf_rn(x2, q, 4.89352518554385e-03f);
    float p = -2.76076847742355e-16f;
    p = __fmaf_rn(x2, p, 2.00018790482477e-13f);
    p = __fmaf_rn(x2, p, -8.60467152213735e-11f);
    p = __fmaf_rn(x2, p, 5.12229709037114e-08f);
    p = __fmaf_rn(x2, p, 1.48572235717979e-05f);
    p = __fmaf_rn(x2, p, 6.37261928875436e-04f);
    p = __fmaf_rn(x2, p, 4.89352455891786e-03f);
    p = __fmul_rn(cx, p);
    float r = __fdiv_rn(p, q);
    return (fabsf(x) < kTiny) ? x : r;
}

#define HBAR() asm volatile("bar.sync 3, 64;" ::: "memory")

// ---------------------------------------------------------------------------
// Warp-specialized fused ESN kernel. One batch per CTA, 192 threads.
//   tid   0..63  : HELPER warps — x staging, u-chains (verified ascending-d),
//                  output STG.
//   tid  64..191 : COMPUTE warps — minimal serial loop: (u LDS pre-bar), bar,
//                  8-deep LDS head, 128-FMA chain, tanh, STS.
// ---------------------------------------------------------------------------
__global__ __launch_bounds__(192, 1) void esn_fused_kernel(
    const float* __restrict__ x,
    const float* __restrict__ W_in,
    const float* __restrict__ b_in,
    const float* __restrict__ W_res,
    const float* __restrict__ b_res,
    float* __restrict__ X)
{
    __shared__ __align__(16) float st[2][N];      // state double buffer
    __shared__ __align__(16) float uring[4][N];   // u values, 2-step lookahead
    __shared__ __align__(16) float xb[2][D];      // x rows (helpers only)

    const int tid = threadIdx.x;
    const int b   = blockIdx.x;
    const float* xrow = x + (size_t)b * T * D;
    float* Xb = X + (size_t)b * T * N;

    if (tid < 64) {
        // ================= HELPER PATH =================
        const int lane = tid;
        const int c0 = lane, c1 = lane + 64;

        float win0[D], win1[D];
#pragma unroll
        for (int d = 0; d < D; d++) {
            win0[d] = W_in[d * N + c0];
            win1[d] = W_in[d * N + c1];
        }
        const float bi0 = b_in[c0], bi1 = b_in[c1];

        // ---- prologue: fill uring[0..2] = u[0..2] ----
#pragma unroll
        for (int s = 0; s < 3; s++) {
            if (s == 2) HBAR();                       // xb[0] reads (s=0) done
            xb[s & 1][lane] = xrow[(size_t)s * D + lane];
            HBAR();
            const float4* xq = reinterpret_cast<const float4*>(xb[s & 1]);
            float a0 = 0.f, a1 = 0.f;
#pragma unroll
            for (int j = 0; j < D / 4; j++) {
                float4 c = xq[j];
                a0 = __fmaf_rn(c.x, win0[4 * j],     a0);
                a0 = __fmaf_rn(c.y, win0[4 * j + 1], a0);
                a0 = __fmaf_rn(c.z, win0[4 * j + 2], a0);
                a0 = __fmaf_rn(c.w, win0[4 * j + 3], a0);
                a1 = __fmaf_rn(c.x, win1[4 * j],     a1);
                a1 = __fmaf_rn(c.y, win1[4 * j + 1], a1);
                a1 = __fmaf_rn(c.z, win1[4 * j + 2], a1);
                a1 = __fmaf_rn(c.w, win1[4 * j + 3], a1);
            }
            uring[s][c0] = __fadd_rn(a0, bi0);
            uring[s][c1] = __fadd_rn(a1, bi1);
        }
        float xreg = xrow[(size_t)3 * D + lane];      // x[3] for step t=1
        __syncthreads();                              // bar A: uring ready
        // compute does t=0 epilogue here
        __syncthreads();                              // bar B

        for (int t = 1; t < T; t++) {
            if (t <= T - 3) {
                xb[t & 1][lane] = xreg;               // stage x[t+2]
            }
            HBAR();
            if (t <= T - 3) {
                const float4* xq =
                    reinterpret_cast<const float4*>(xb[t & 1]);
                float a0 = 0.f, a1 = 0.f;
#pragma unroll
                for (int j = 0; j < D / 4; j++) {
                    float4 c = xq[j];
                    a0 = __fmaf_rn(c.x, win0[4 * j],     a0);
                    a0 = __fmaf_rn(c.y, win0[4 * j + 1], a0);
                    a0 = __fmaf_rn(c.z, win0[4 * j + 2], a0);
                    a0 = __fmaf_rn(c.w, win0[4 * j + 3], a0);
                    a1 = __fmaf_rn(c.x, win1[4 * j],     a1);
                    a1 = __fmaf_rn(c.y, win1[4 * j + 1], a1);
                    a1 = __fmaf_rn(c.z, win1[4 * j + 2], a1);
                    a1 = __fmaf_rn(c.w, win1[4 * j + 3], a1);
                }
                uring[(t + 2) & 3][c0] = __fadd_rn(a0, bi0);
                uring[(t + 2) & 3][c1] = __fadd_rn(a1, bi1);
            }
            if (t <= T - 4) xreg = xrow[(size_t)(t + 3) * D + lane];
            if (t >= 2) {
                // store X[t-1] (st[(t-1)&1] stable until after this barrier)
                float v0 = st[(t - 1) & 1][c0];
                float v1 = st[(t - 1) & 1][c1];
                Xb[(size_t)(t - 1) * N + c0] = v0;
                Xb[(size_t)(t - 1) * N + c1] = v1;
            }
            __syncthreads();
        }
    } else {
        // ================= COMPUTE PATH =================
        const int n = tid - 64;

        float w[N];
#pragma unroll
        for (int k = 0; k < N; k++) w[k] = W_res[k * N + n];
        const float brv = b_res[n];

        __syncthreads();                              // bar A: uring ready

        // t = 0 epilogue
        float xv = __fmul_rn(LEAK, tanh_xla(uring[0][n]));
        st[0][n] = xv;
        Xb[n] = xv;                                   // X[0]
        float uthis = uring[1][n];                    // pre-bar LDS for t=1
        __syncthreads();                              // bar B

        for (int t = 1; t < T; t++) {
            // halfx off the tail; exact mul
            const float halfx = __fmul_rn(1.0f - LEAK, xv);

            const float4* xp4 =
                reinterpret_cast<const float4*>(st[(t - 1) & 1]);
            // depth-8 head: all 8 LDS issue immediately; chain starts on f[0]
            float4 f[8];
#pragma unroll
            for (int i = 0; i < 8; i++) f[i] = xp4[i];

            float acc = 0.f;
#pragma unroll
            for (int j = 0; j < 32; j++) {
                float4 c = f[0];
#pragma unroll
                for (int i = 0; i < 7; i++) f[i] = f[i + 1];
                if (j < 24) f[7] = xp4[j + 8];
                acc = __fmaf_rn(c.x, w[4 * j],     acc);
                acc = __fmaf_rn(c.y, w[4 * j + 1], acc);
                acc = __fmaf_rn(c.z, w[4 * j + 2], acc);
                acc = __fmaf_rn(c.w, w[4 * j + 3], acc);
            }

            float arg = __fadd_rn(__fadd_rn(uthis, acc), brv);
            float th  = tanh_xla(arg);
            xv = __fadd_rn(halfx, __fmul_rn(LEAK, th));

            st[t & 1][n] = xv;
            // pre-bar LDS of u for step t+1 (slot stable since step t-1)
            uthis = uring[(t + 1) & 3][n];
            __syncthreads();
        }
        Xb[(size_t)(T - 1) * N + n] = xv;             // X[T-1]
    }
}

// ---------------------------------------------------------------------------
extern "C" void kernel_launch(void* const* d_in, const int* in_sizes, int n_in,
                              void* d_out, int out_size)
{
    const float* x     = (const float*)d_in[0];
    const float* W_in  = (const float*)d_in[1];
    const float* b_in  = (const float*)d_in[2];
    const float* W_res = (const float*)d_in[3];
    const float* b_res = (const float*)d_in[4];
    float* X = (float*)d_out;

    esn_fused_kernel<<<B, 192>>>(x, W_in, b_in, W_res, b_res, X);
}

// round 16
// speedup vs baseline: 1.3545x; 1.3321x over previous
#include <cuda_runtime.h>
#include <cuda_bf16.h>
#include <math.h>

// Problem constants
#define B    256
#define T    2048
#define D    64
#define N    128
#define LEAK 0.5f

// ---------------------------------------------------------------------------
// XLA ElementalIrEmitter::EmitTanh replica — VERIFIED BITWISE vs reference.
// q-polynomial first so ptxas can launch the divide's RCP during the p-chain.
// ---------------------------------------------------------------------------
__device__ __forceinline__ float tanh_xla(float x) {
    const float kClamp = 7.99881172180175781f;
    const float kTiny  = 0.0004f;
    float cx = fminf(fmaxf(x, -kClamp), kClamp);
    float x2 = __fmul_rn(cx, cx);
    float q = 1.19825839466702e-06f;
    q = __fmaf_rn(x2, q, 1.18534705686654e-04f);
    q = __fmaf_rn(x2, q, 2.26843463243900e-03f);
    q = __fmaf_rn(x2, q, 4.89352518554385e-03f);
    float p = -2.76076847742355e-16f;
    p = __fmaf_rn(x2, p, 2.00018790482477e-13f);
    p = __fmaf_rn(x2, p, -8.60467152213735e-11f);
    p = __fmaf_rn(x2, p, 5.12229709037114e-08f);
    p = __fmaf_rn(x2, p, 1.48572235717979e-05f);
    p = __fmaf_rn(x2, p, 6.37261928875436e-04f);
    p = __fmaf_rn(x2, p, 4.89352455891786e-03f);
    p = __fmul_rn(cx, p);
    float r = __fdiv_rn(p, q);
    return (fabsf(x) < kTiny) ? x : r;
}

#define BAR_ALL()  asm volatile("bar.sync 0, 192;" ::: "memory")   // full rendezvous
#define BAR_CMP()  asm volatile("bar.sync 1, 128;" ::: "memory")   // compute-only
#define BAR_HLP()  asm volatile("bar.sync 3, 64;"  ::: "memory")   // helper-only

// ---------------------------------------------------------------------------
// Warp-specialized fused ESN kernel. One batch per CTA, 192 threads.
//   tid   0..63  : HELPER warps — 2-step windows: stage x rows (8-deep ring),
//                  produce u[2j+4], u[2j+5] (8-deep u-ring), LDG prefetched
//                  2 windows (~4 steps) ahead. Verified ascending-d chains.
//   tid  64..191 : COMPUTE warps — serial loop; barrier = compute-only after
//                  even steps, full rendezvous only every 2nd step. X output
//                  stored directly from compute registers.
// ---------------------------------------------------------------------------
__global__ __launch_bounds__(192, 1) void esn_fused_kernel(
    const float* __restrict__ x,
    const float* __restrict__ W_in,
    const float* __restrict__ b_in,
    const float* __restrict__ W_res,
    const float* __restrict__ b_res,
    float* __restrict__ X)
{
    __shared__ __align__(16) float st[2][N];      // state double buffer
    __shared__ __align__(16) float uring[8][N];   // u ring, depth 8
    __shared__ __align__(16) float xb[8][D];      // x-row ring (helpers only)

    const int tid = threadIdx.x;
    const int b   = blockIdx.x;
    const float* xrow = x + (size_t)b * T * D;
    float* Xb = X + (size_t)b * T * N;

    if (tid < 64) {
        // ================= HELPER PATH =================
        const int lane = tid;
        const int c0 = lane, c1 = lane + 64;

        float win0[D], win1[D];
#pragma unroll
        for (int d = 0; d < D; d++) {
            win0[d] = W_in[d * N + c0];
            win1[d] = W_in[d * N + c1];
        }
        const float bi0 = b_in[c0], bi1 = b_in[c1];

        // prologue: stage x rows 0..5, produce u[0..3]
#pragma unroll
        for (int s = 0; s < 6; s++)
            xb[s][lane] = xrow[(size_t)s * D + lane];
        BAR_HLP();
#pragma unroll
        for (int s = 0; s < 4; s++) {
            const float4* xq = reinterpret_cast<const float4*>(xb[s]);
            float a0 = 0.f, a1 = 0.f;
#pragma unroll
            for (int j = 0; j < D / 4; j++) {
                float4 c = xq[j];
                a0 = __fmaf_rn(c.x, win0[4 * j],     a0);
                a0 = __fmaf_rn(c.y, win0[4 * j + 1], a0);
                a0 = __fmaf_rn(c.z, win0[4 * j + 2], a0);
                a0 = __fmaf_rn(c.w, win0[4 * j + 3], a0);
                a1 = __fmaf_rn(c.x, win1[4 * j],     a1);
                a1 = __fmaf_rn(c.y, win1[4 * j + 1], a1);
                a1 = __fmaf_rn(c.z, win1[4 * j + 2], a1);
                a1 = __fmaf_rn(c.w, win1[4 * j + 3], a1);
            }
            uring[s][c0] = __fadd_rn(a0, bi0);
            uring[s][c1] = __fadd_rn(a1, bi1);
        }
        // prefetch x rows 6,7
        float r6 = xrow[(size_t)6 * D + lane];
        float r7 = xrow[(size_t)7 * D + lane];

        for (int j = 0; j < T / 2; j++) {
            BAR_ALL();                       // window rendezvous (huge slack)
            const int t4 = 2 * j + 4, t5 = 2 * j + 5;
            const int s6 = 2 * j + 6, s7 = 2 * j + 7;
            if (s6 < T) xb[s6 & 7][lane] = r6;
            if (s7 < T) xb[s7 & 7][lane] = r7;
            BAR_HLP();
#pragma unroll
            for (int h = 0; h < 2; h++) {
                const int tt = h ? t5 : t4;
                if (tt < T) {
                    const float4* xq =
                        reinterpret_cast<const float4*>(xb[tt & 7]);
                    float a0 = 0.f, a1 = 0.f;
#pragma unroll
                    for (int jj = 0; jj < D / 4; jj++) {
                        float4 c = xq[jj];
                        a0 = __fmaf_rn(c.x, win0[4 * jj],     a0);
                        a0 = __fmaf_rn(c.y, win0[4 * jj + 1], a0);
                        a0 = __fmaf_rn(c.z, win0[4 * jj + 2], a0);
                        a0 = __fmaf_rn(c.w, win0[4 * jj + 3], a0);
                        a1 = __fmaf_rn(c.x, win1[4 * jj],     a1);
                        a1 = __fmaf_rn(c.y, win1[4 * jj + 1], a1);
                        a1 = __fmaf_rn(c.z, win1[4 * jj + 2], a1);
                        a1 = __fmaf_rn(c.w, win1[4 * jj + 3], a1);
                    }
                    uring[tt & 7][c0] = __fadd_rn(a0, bi0);
                    uring[tt & 7][c1] = __fadd_rn(a1, bi1);
                }
            }
            if (s6 + 2 < T) r6 = xrow[(size_t)(s6 + 2) * D + lane];
            if (s7 + 2 < T) r7 = xrow[(size_t)(s7 + 2) * D + lane];
        }
    } else {
        // ================= COMPUTE PATH =================
        const int n = tid - 64;

        float w[N];
#pragma unroll
        for (int k = 0; k < N; k++) w[k] = W_res[k * N + n];
        const float brv = b_res[n];
        float* xoP = Xb + n;

        BAR_ALL();                                   // R_0

        // t = 0 epilogue
        float xv = __fmul_rn(LEAK, tanh_xla(uring[0][n]));
        st[0][n] = xv;
        xoP[0] = xv;
        float uthis = uring[1][n];
        BAR_CMP();

        // generic step body (bitwise-verified semantics)
#define STEP(T_IDX, RD_PAR, WR_PAR)                                        \
        {                                                                  \
            const float halfx = __fmul_rn(1.0f - LEAK, xv);                \
            const float4* xp4 =                                            \
                reinterpret_cast<const float4*>(st[RD_PAR]);               \
            float4 f[8];                                                   \
            _Pragma("unroll")                                              \
            for (int i = 0; i < 8; i++) f[i] = xp4[i];                     \
            float acc = 0.f;                                               \
            _Pragma("unroll")                                              \
            for (int jj = 0; jj < 32; jj++) {                              \
                float4 c = f[0];                                           \
                _Pragma("unroll")                                          \
                for (int i = 0; i < 7; i++) f[i] = f[i + 1];               \
                if (jj < 24) f[7] = xp4[jj + 8];                           \
                acc = __fmaf_rn(c.x, w[4 * jj],     acc);                  \
                acc = __fmaf_rn(c.y, w[4 * jj + 1], acc);                  \
                acc = __fmaf_rn(c.z, w[4 * jj + 2], acc);                  \
                acc = __fmaf_rn(c.w, w[4 * jj + 3], acc);                  \
            }                                                              \
            float arg = __fadd_rn(__fadd_rn(uthis, acc), brv);             \
            float th  = tanh_xla(arg);                                     \
            xv = __fadd_rn(halfx, __fmul_rn(LEAK, th));                    \
            st[WR_PAR][n] = xv;                                            \
            xoP[(size_t)(T_IDX) * N] = xv;                                 \
            uthis = uring[((T_IDX) + 1) & 7][n];                           \
        }

        // t = 1 (peeled)
        STEP(1, 0, 1)

        for (int j = 1; j < T / 2; j++) {
            BAR_ALL();                               // R_j (helpers早 arrive)
            const int te = 2 * j;
            STEP(te, 1, 0)                           // even step
            BAR_CMP();
            STEP(te + 1, 0, 1)                       // odd step
        }
#undef STEP
    }
}

// ---------------------------------------------------------------------------
extern "C" void kernel_launch(void* const* d_in, const int* in_sizes, int n_in,
                              void* d_out, int out_size)
{
    const float* x     = (const float*)d_in[0];
    const float* W_in  = (const float*)d_in[1];
    const float* b_in  = (const float*)d_in[2];
    const float* W_res = (const float*)d_in[3];
    const float* b_res = (const float*)d_in[4];
    float* X = (float*)d_out;

    esn_fused_kernel<<<B, 192>>>(x, W_in, b_in, W_res, b_res, X);
}